// round 1
// baseline (speedup 1.0000x reference)
#include <cuda_runtime.h>
#include <cstdint>

// HashGrid3D: 16-level Instant-NGP style hash grid encode.
// xyt: (1048576, 3) fp32 in [0,1); tables: (16, 524288, 2) fp32.
// out: (1048576, 32) fp32.
//
// hash(c) = (cx*1 ^ cy*2654435761 ^ cz*805459861) & (T-1), T = 2^19.

#define T_SIZE 524288u
#define HMASK  (T_SIZE - 1u)
#define NPTS   1048576

__global__ void __launch_bounds__(256) hashgrid3d_kernel(
    const float* __restrict__ xyt,
    const float2* __restrict__ tables,
    float4* __restrict__ out,
    int n)
{
    const int p = blockIdx.x * blockDim.x + threadIdx.x;
    if (p >= n) return;

    const float x = xyt[3 * p + 0];
    const float y = xyt[3 * p + 1];
    const float z = xyt[3 * p + 2];

    // round(16 * (32)^(l/15)) for l in 0..15
    const int RES[16] = {16, 20, 25, 32, 40, 51, 64, 81,
                         102, 128, 161, 203, 256, 323, 406, 512};

    float res[32];

#pragma unroll
    for (int l = 0; l < 16; ++l) {
        const int N = RES[l];
        const float2* __restrict__ tbl = tables + (size_t)l * T_SIZE;

        const float fN = (float)N;
        float sx = x * fN, sy = y * fN, sz = z * fN;
        float fx = floorf(sx), fy = floorf(sy), fz = floorf(sz);
        float tx = sx - fx, ty = sy - fy, tz = sz - fz;

        int ix = (int)fx, iy = (int)fy, iz = (int)fz;
        // reference applies % N to the base corner too (handles the s==N
        // rounding edge); values are always in [0, N] here.
        if (ix >= N) ix -= N;
        if (iy >= N) iy -= N;
        if (iz >= N) iz -= N;
        int ix1 = ix + 1; if (ix1 >= N) ix1 -= N;
        int iy1 = iy + 1; if (iy1 >= N) iy1 -= N;
        int iz1 = iz + 1; if (iz1 >= N) iz1 -= N;

        const uint32_t hx0 = (uint32_t)ix;                    // prime = 1
        const uint32_t hx1 = (uint32_t)ix1;
        const uint32_t hy0 = (uint32_t)iy  * 2654435761u;
        const uint32_t hy1 = (uint32_t)iy1 * 2654435761u;
        const uint32_t hz0 = (uint32_t)iz  * 805459861u;
        const uint32_t hz1 = (uint32_t)iz1 * 805459861u;

        // 8 independent gathers -> MLP within the level
        const float2 g000 = __ldg(tbl + ((hx0 ^ hy0 ^ hz0) & HMASK));
        const float2 g100 = __ldg(tbl + ((hx1 ^ hy0 ^ hz0) & HMASK));
        const float2 g010 = __ldg(tbl + ((hx0 ^ hy1 ^ hz0) & HMASK));
        const float2 g110 = __ldg(tbl + ((hx1 ^ hy1 ^ hz0) & HMASK));
        const float2 g001 = __ldg(tbl + ((hx0 ^ hy0 ^ hz1) & HMASK));
        const float2 g101 = __ldg(tbl + ((hx1 ^ hy0 ^ hz1) & HMASK));
        const float2 g011 = __ldg(tbl + ((hx0 ^ hy1 ^ hz1) & HMASK));
        const float2 g111 = __ldg(tbl + ((hx1 ^ hy1 ^ hz1) & HMASK));

        const float ux = 1.0f - tx, uy = 1.0f - ty, uz = 1.0f - tz;
        const float wy0z0 = uy * uz, wy1z0 = ty * uz;
        const float wy0z1 = uy * tz, wy1z1 = ty * tz;

        const float w000 = ux * wy0z0, w100 = tx * wy0z0;
        const float w010 = ux * wy1z0, w110 = tx * wy1z0;
        const float w001 = ux * wy0z1, w101 = tx * wy0z1;
        const float w011 = ux * wy1z1, w111 = tx * wy1z1;

        float r0 = w000 * g000.x;
        float r1 = w000 * g000.y;
        r0 = fmaf(w100, g100.x, r0);  r1 = fmaf(w100, g100.y, r1);
        r0 = fmaf(w010, g010.x, r0);  r1 = fmaf(w010, g010.y, r1);
        r0 = fmaf(w110, g110.x, r0);  r1 = fmaf(w110, g110.y, r1);
        r0 = fmaf(w001, g001.x, r0);  r1 = fmaf(w001, g001.y, r1);
        r0 = fmaf(w101, g101.x, r0);  r1 = fmaf(w101, g101.y, r1);
        r0 = fmaf(w011, g011.x, r0);  r1 = fmaf(w011, g011.y, r1);
        r0 = fmaf(w111, g111.x, r0);  r1 = fmaf(w111, g111.y, r1);

        res[2 * l + 0] = r0;
        res[2 * l + 1] = r1;
    }

    // each thread owns one full 128B output line
    float4* o = out + (size_t)p * 8;
#pragma unroll
    for (int i = 0; i < 8; ++i)
        o[i] = make_float4(res[4 * i + 0], res[4 * i + 1],
                           res[4 * i + 2], res[4 * i + 3]);
}

extern "C" void kernel_launch(void* const* d_in, const int* in_sizes, int n_in,
                              void* d_out, int out_size)
{
    const float*  xyt    = (const float*)d_in[0];
    const float2* tables = (const float2*)d_in[1];
    float4*       out    = (float4*)d_out;

    const int n = in_sizes[0] / 3;  // 1048576 points
    const int threads = 256;
    const int blocks = (n + threads - 1) / threads;

    hashgrid3d_kernel<<<blocks, threads>>>(xyt, tables, out, n);
}